// round 9
// baseline (speedup 1.0000x reference)
#include <cuda_runtime.h>

#define NN 8192
#define NE 16384
#define DD 128
#define RR 64
#define BB 16
#define GRID 148
#define NTHR 512
#define TROWS 256
#define WS 132              // sW k-row stride in words
#define XT 260              // xsT k-row stride in words (256 rows + 4 pad)

typedef unsigned long long u64;

// ---------------- device scratch (no allocations allowed) ----------------
__device__ __align__(16) float g_fullW[RR*DD*DD];   // 4 MB expanded basis
__device__ int g_comb[NN*RR];                       // (tgt,rel) bucket counts
__device__ int g_cnt8[RR*8];                        // banked relation counters
__device__ int g_off8[RR*8];                        // scanned bank offsets
__device__ int g_relcnt[RR], g_reloff[RR];
__device__ int g_src[NE], g_tgt[NE];
__device__ int g_sorted[NE];
__device__ int g_tiles[1024], g_ntiles;
__device__ int g_is64;
__device__ int g_bar[8];
__device__ int g_sdone, g_bdone, g_scan;
__device__ unsigned g_ticket;

// ---------------- helpers ----------------
__device__ __forceinline__ u64 pack2(float x) {
    u64 r; asm("mov.b64 %0, {%1, %1};" : "=l"(r) : "f"(x)); return r;
}
__device__ __forceinline__ void ffma2(u64& d, u64 a, u64 b) {
    asm("fma.rn.f32x2 %0, %1, %2, %0;" : "+l"(d) : "l"(a), "l"(b));
}
__device__ __forceinline__ float2 unpack2(u64 v) {
    float2 f; asm("mov.b64 {%0, %1}, %2;" : "=f"(f.x), "=f"(f.y) : "l"(v)); return f;
}
__device__ __forceinline__ void red4(float* p, float a, float b, float c, float d) {
    asm volatile("red.global.add.v4.f32 [%0], {%1,%2,%3,%4};"
                 :: "l"(p), "f"(a), "f"(b), "f"(c), "f"(d) : "memory");
}
__device__ __forceinline__ int ld_cg(const int* p) {
    int v; asm volatile("ld.global.cg.b32 %0, [%1];" : "=r"(v) : "l"(p) : "memory"); return v;
}

// ---------------- the single persistent kernel ----------------
__global__ void __launch_bounds__(NTHR, 1) k_fused(
        const float* __restrict__ inp, const void* __restrict__ dep,
        const void* __restrict__ ei,   const float* __restrict__ weight,
        const float* __restrict__ wcomp, const float* __restrict__ sw,
        const float* __restrict__ bias, float* __restrict__ out) {
    extern __shared__ float sm[];
    float* sW    = sm;                    // 129*132 = 17028 floats
    float* xsT   = sm + 17028;            // 129*260 = 33540 floats (transposed x)
    int*   s_src = (int*)(xsT + 33540);
    float* s_inv = (float*)(s_src + TROWS);
    int*   s_tgt = (int*)(s_inv + TROWS);
    int*   s_misc= (int*)(s_tgt + TROWS);

    const int bid = blockIdx.x, tid = threadIdx.x;
    const int gtid = bid*NTHR + tid, G = GRID*NTHR;
    const int wid = tid >> 5, lane = tid & 31;

    // ---- phase 0: zero scratch & output, reset flags, quick index-width sniff ----
    {
        const int4 z4 = make_int4(0,0,0,0);
        for (int k = gtid; k < NN*RR/4; k += G) ((int4*)g_comb)[k] = z4;
        const float4 f4 = make_float4(0.f,0.f,0.f,0.f);
        for (int k = gtid; k < NN*DD/4; k += G) ((float4*)out)[k] = f4;
        if (gtid < RR*8) g_cnt8[gtid] = 0;
        if (gtid == 0) { g_ticket = 0u; g_sdone = 0; g_bdone = 0; g_scan = 0; }
        if (bid == 0 && wid == 0) {       // 32-sample sniff: int64 iff all hi words 0
            const unsigned* eu = (const unsigned*)ei;
            unsigned any = (eu[2*lane + 1] != 0u) ? 1u : 0u;
            any = __ballot_sync(0xffffffffu, any);
            if (lane == 0) g_is64 = (any == 0u) ? 1 : 0;
        }
    }
    __threadfence();
    __syncthreads();
    if (tid == 0) {
        atomicAdd(&g_bar[0], 1);
        while (ld_cg(&g_bar[0]) < GRID) __nanosleep(32);
    }
    __syncthreads();

    // ---- fork: blocks 0..31 = edge chain; blocks 32..147 = basis expansion ----
    if (bid < 32) {
        const int e = bid*NTHR + tid;
        int rel, sN, tN;
        if (g_is64) {
            rel = (int)((const long long*)dep)[e];
            sN  = (int)((const long long*)ei)[e];
            tN  = (int)((const long long*)ei)[NE + e];
        } else {
            rel = ((const int*)dep)[e];
            sN  = ((const int*)ei)[e];
            tN  = ((const int*)ei)[NE + e];
        }
        g_src[e] = sN; g_tgt[e] = tN;
        atomicAdd(&g_comb[tN*RR + rel], 1);
        const int bank = bid & 7;
        const int rk = atomicAdd(&g_cnt8[rel*8 + bank], 1);

        __threadfence();
        __syncthreads();
        if (tid == 0) atomicAdd(&g_bar[1], 1);

        if (bid == 0) {
            if (tid == 0) while (ld_cg(&g_bar[1]) < 32) __nanosleep(32);
            __syncthreads();
            if (tid < 32) {                       // parallel scan + tile list
                int vals[16], local = 0;
                #pragma unroll
                for (int k = 0; k < 16; k++) {
                    int c = g_cnt8[tid*16 + k];
                    vals[k] = local; local += c;
                }
                int x = local;
                #pragma unroll
                for (int d = 1; d < 32; d <<= 1) {
                    int y = __shfl_up_sync(0xffffffffu, x, d);
                    if (lane >= d) x += y;
                }
                const int excl = x - local;
                #pragma unroll
                for (int k = 0; k < 16; k++) g_off8[tid*16 + k] = excl + vals[k];
                const int r0 = 2*tid, r1 = 2*tid + 1;
                const int cnt0 = vals[8], cnt1 = local - vals[8];
                g_relcnt[r0] = cnt0; g_relcnt[r1] = cnt1;
                g_reloff[r0] = excl; g_reloff[r1] = excl + vals[8];
                const int nt0 = (cnt0 + TROWS-1)/TROWS, nt1 = (cnt1 + TROWS-1)/TROWS;
                const int ntl = nt0 + nt1;
                int ts = ntl;
                #pragma unroll
                for (int d = 1; d < 32; d <<= 1) {
                    int y = __shfl_up_sync(0xffffffffu, ts, d);
                    if (lane >= d) ts += y;
                }
                const int tbase = ts - ntl;
                for (int c = 0; c < nt0; c++) g_tiles[tbase + c] = (r0 << 8) | c;
                for (int c = 0; c < nt1; c++) g_tiles[tbase + nt0 + c] = (r1 << 8) | c;
                if (tid == 31) g_ntiles = ts;
            }
            __threadfence();
            __syncthreads();
            if (tid == 0) atomicExch(&g_scan, 1);
        } else {
            if (tid == 0) while (ld_cg(&g_scan) == 0) __nanosleep(32);
            __syncthreads();
        }
        g_sorted[g_off8[rel*8 + bank] + rk] = e;
        __threadfence();
        __syncthreads();
        if (tid == 0) atomicAdd(&g_sdone, 1);
    } else {
        const int j = tid & 127, rh = tid >> 7;          // rh 0..3 -> 16 r's each
        for (int k = tid; k < RR*BB; k += NTHR) sm[k] = wcomp[k];
        __syncthreads();
        const int i1 = bid - 32;
        const int npass = (i1 < 12) ? 2 : 1;
        for (int ps = 0; ps < npass; ps++) {
            const int i = i1 + ps*116;
            float wr[BB];
            #pragma unroll
            for (int b = 0; b < BB; b++) wr[b] = weight[(b*DD + i)*DD + j];
            #pragma unroll 4
            for (int r = rh*16; r < rh*16 + 16; r++) {
                float a = 0.f;
                #pragma unroll
                for (int b = 0; b < BB; b++) a += sm[r*BB + b] * wr[b];
                g_fullW[((size_t)r*DD + i)*DD + j] = a;
            }
        }
        __threadfence();
        __syncthreads();
        if (tid == 0) atomicAdd(&g_bdone, 1);
    }

    // ---- ticket loop: self tiles (0..31) first, then gated edge tiles ----
    // thread tile: 8 rows x 8 cols. warp = 2 tr x 16 tc; warp spans 16 rows.
    const int tc = lane & 15;
    const int tr = 2*wid + (lane >> 4);        // 0..31 -> rows 8tr..8tr+7
    const float* last_w = (const float*)0;
    bool edges_ok = false;
    int ntiles = 0;

    for (;;) {
        __syncthreads();                       // previous tile fully consumed
        if (tid == 0) s_misc[0] = (int)atomicAdd(&g_ticket, 1u);
        __syncthreads();
        const int t = s_misc[0];
        const bool is_self = (t < NN/TROWS);   // 32 self tiles

        int rel = 0, base, cnt, off = 0;
        if (is_self) { base = t*TROWS; cnt = NN; }
        else {
            if (!edges_ok) {                   // gate: scatter + basis complete
                if (tid == 0)
                    while (ld_cg(&g_sdone) < 32 || ld_cg(&g_bdone) < 116)
                        __nanosleep(64);
                __syncthreads();
                edges_ok = true;
                ntiles = g_ntiles;
            }
            if (t - NN/TROWS >= ntiles) break;
            const int tt = g_tiles[t - NN/TROWS];
            rel = tt >> 8; base = (tt & 255)*TROWS;
            cnt = g_relcnt[rel]; off = g_reloff[rel];
        }

        if (tid < TROWS) {                     // per-row metadata (256 rows)
            if (is_self) {
                s_src[tid] = base + tid; s_tgt[tid] = base + tid; s_inv[tid] = 1.f;
            } else {
                const int le = base + tid;
                const bool v = le < cnt;
                const int e = g_sorted[off + (v ? le : base)];
                const int sN = g_src[e], tN = g_tgt[e];
                s_src[tid] = sN; s_tgt[tid] = tN;
                s_inv[tid] = v ? 1.0f/(float)g_comb[tN*RR + rel] : 0.f;
            }
        }
        // stage W [128k x 128c] (stride WS), skipped when unchanged
        const float* wsrc = is_self ? sw : g_fullW + (size_t)rel*DD*DD;
        if (wsrc != last_w) {
            if (is_self) {                     // transpose sw on the fly
                #pragma unroll
                for (int p = 0; p < 8; p++) {
                    const int m = tid + p*NTHR;          // < 4096
                    const int jr = m & 127, k4 = m >> 7;
                    const float4 v = ((const float4*)sw)[jr*32 + k4];
                    sW[(4*k4 + 0)*WS + jr] = v.x;
                    sW[(4*k4 + 1)*WS + jr] = v.y;
                    sW[(4*k4 + 2)*WS + jr] = v.z;
                    sW[(4*k4 + 3)*WS + jr] = v.w;
                }
            } else {
                #pragma unroll
                for (int p = 0; p < 8; p++) {
                    const int m = tid + p*NTHR;          // < 4096
                    const int k = m >> 5, jj = m & 31;
                    ((float4*)sW)[k*33 + jj] = ((const float4*)wsrc)[m];
                }
            }
            last_w = wsrc;
        }
        __syncthreads();

        // gather x transposed: thread -> (row = tid>>1, k-half = tid&1)
        {
            const int r = tid >> 1, half = tid & 1;
            const float4* ip = (const float4*)(inp + (size_t)s_src[r]*DD);
            #pragma unroll 4
            for (int q = 0; q < 16; q++) {
                const int k4 = half*16 + q;
                const float4 v = ip[k4];
                xsT[(4*k4 + 0)*XT + r] = v.x;
                xsT[(4*k4 + 1)*XT + r] = v.y;
                xsT[(4*k4 + 2)*XT + r] = v.z;
                xsT[(4*k4 + 3)*XT + r] = v.w;
            }
        }
        __syncthreads();

        // warps whose 16 rows are all past cnt skip compute entirely
        if (is_self || base + 16*wid < cnt) {
            u64 acc[32];                       // [row 0..7][colpair 0..3]
            #pragma unroll
            for (int q = 0; q < 32; q++) acc[q] = 0ull;

            const float* xp = xsT + 8*tr;
            const float* wp = sW + 8*tc;
            // two row-group half-steps per k: peak live regs ~90 (no spills)
            #pragma unroll 2
            for (int k = 0; k < DD; k++) {
                const ulonglong2 wa = *(const ulonglong2*)(wp + k*WS);
                const ulonglong2 wb = *(const ulonglong2*)(wp + k*WS + 4);
                {   // rows 0..3
                    const float4 xa = *(const float4*)(xp + k*XT);
                    const u64 x0 = pack2(xa.x), x1 = pack2(xa.y);
                    const u64 x2 = pack2(xa.z), x3 = pack2(xa.w);
                    ffma2(acc[ 0], x0, wa.x); ffma2(acc[ 1], x0, wa.y);
                    ffma2(acc[ 2], x0, wb.x); ffma2(acc[ 3], x0, wb.y);
                    ffma2(acc[ 4], x1, wa.x); ffma2(acc[ 5], x1, wa.y);
                    ffma2(acc[ 6], x1, wb.x); ffma2(acc[ 7], x1, wb.y);
                    ffma2(acc[ 8], x2, wa.x); ffma2(acc[ 9], x2, wa.y);
                    ffma2(acc[10], x2, wb.x); ffma2(acc[11], x2, wb.y);
                    ffma2(acc[12], x3, wa.x); ffma2(acc[13], x3, wa.y);
                    ffma2(acc[14], x3, wb.x); ffma2(acc[15], x3, wb.y);
                }
                {   // rows 4..7
                    const float4 xb = *(const float4*)(xp + k*XT + 4);
                    const u64 x4 = pack2(xb.x), x5 = pack2(xb.y);
                    const u64 x6 = pack2(xb.z), x7 = pack2(xb.w);
                    ffma2(acc[16], x4, wa.x); ffma2(acc[17], x4, wa.y);
                    ffma2(acc[18], x4, wb.x); ffma2(acc[19], x4, wb.y);
                    ffma2(acc[20], x5, wa.x); ffma2(acc[21], x5, wa.y);
                    ffma2(acc[22], x5, wb.x); ffma2(acc[23], x5, wb.y);
                    ffma2(acc[24], x6, wa.x); ffma2(acc[25], x6, wa.y);
                    ffma2(acc[26], x6, wb.x); ffma2(acc[27], x6, wb.y);
                    ffma2(acc[28], x7, wa.x); ffma2(acc[29], x7, wa.y);
                    ffma2(acc[30], x7, wb.x); ffma2(acc[31], x7, wb.y);
                }
            }

            // epilogue: two red.v4 per valid row (8 contiguous cols)
            float4 bb0 = make_float4(0.f,0.f,0.f,0.f);
            float4 bb1 = bb0;
            if (is_self) {
                bb0 = __ldg((const float4*)bias + 2*tc);
                bb1 = __ldg((const float4*)bias + 2*tc + 1);
            }
            #pragma unroll
            for (int rr = 0; rr < 8; rr++) {
                const int r = 8*tr + rr;
                const float inv = s_inv[r];
                if (inv != 0.f) {
                    const float2 c0 = unpack2(acc[4*rr + 0]);
                    const float2 c1 = unpack2(acc[4*rr + 1]);
                    const float2 c2 = unpack2(acc[4*rr + 2]);
                    const float2 c3 = unpack2(acc[4*rr + 3]);
                    float* op = out + (size_t)s_tgt[r]*DD + 8*tc;
                    red4(op,     c0.x*inv + bb0.x, c0.y*inv + bb0.y,
                                 c1.x*inv + bb0.z, c1.y*inv + bb0.w);
                    red4(op + 4, c2.x*inv + bb1.x, c2.y*inv + bb1.y,
                                 c3.x*inv + bb1.z, c3.y*inv + bb1.w);
                }
            }
        }
    }

    // ---- epilogue: last block resets barrier slots for graph replay ----
    __threadfence();
    __syncthreads();
    if (tid == 0) {
        const int done = atomicAdd(&g_bar[7], 1);
        if (done == GRID - 1) {
            #pragma unroll
            for (int p = 0; p < 8; p++) g_bar[p] = 0;
            __threadfence();
        }
    }
}

// ---------------- launch ----------------
extern "C" void kernel_launch(void* const* d_in, const int* in_sizes, int n_in,
                              void* d_out, int out_size) {
    const float* inp    = (const float*)d_in[0];
    const void*  dep    = d_in[1];
    const void*  ei     = d_in[2];
    const float* weight = (const float*)d_in[3];
    const float* wcomp  = (const float*)d_in[4];
    const float* sw     = (const float*)d_in[5];
    const float* bias   = (const float*)d_in[6];
    float* out = (float*)d_out;

    const int SMEM = (17028 + 33540 + TROWS*3 + 8) * 4;   // ~205.5 KB
    cudaFuncSetAttribute(k_fused, cudaFuncAttributeMaxDynamicSharedMemorySize, SMEM);

    k_fused<<<GRID, NTHR, SMEM>>>(inp, dep, ei, weight, wcomp, sw, bias, out);
}

// round 10
// speedup vs baseline: 1.0570x; 1.0570x over previous
#include <cuda_runtime.h>

#define NN 8192
#define NE 16384
#define DD 128
#define RR 64
#define BB 16
#define GRID 148
#define NTHR 256
#define TROWS 128           // rows per tile
#define WS 132              // sW k-row stride in words
#define XT 132              // xsT k-row stride in words (128 rows + 4 pad)

typedef unsigned long long u64;

// ---------------- device scratch (no allocations allowed) ----------------
__device__ __align__(16) float g_fullW[RR*DD*DD];   // 4 MB expanded basis
__device__ int g_comb[NN*RR];                       // (tgt,rel) bucket counts
__device__ int g_cnt8[RR*8];                        // banked relation counters
__device__ int g_off8[RR*8];                        // scanned bank offsets
__device__ int g_relcnt[RR], g_reloff[RR];
__device__ int g_src[NE], g_tgt[NE];
__device__ int g_sorted[NE];
__device__ int g_tiles[1024], g_ntiles;
__device__ int g_is64;
__device__ int g_bar[8];
__device__ int g_sdone, g_bdone, g_scan;
__device__ unsigned g_ticket;

// ---------------- helpers ----------------
__device__ __forceinline__ u64 pack2(float x) {
    u64 r; asm("mov.b64 %0, {%1, %1};" : "=l"(r) : "f"(x)); return r;
}
__device__ __forceinline__ void ffma2(u64& d, u64 a, u64 b) {
    asm("fma.rn.f32x2 %0, %1, %2, %0;" : "+l"(d) : "l"(a), "l"(b));
}
__device__ __forceinline__ float2 unpack2(u64 v) {
    float2 f; asm("mov.b64 {%0, %1}, %2;" : "=f"(f.x), "=f"(f.y) : "l"(v)); return f;
}
__device__ __forceinline__ void red4(float* p, float a, float b, float c, float d) {
    asm volatile("red.global.add.v4.f32 [%0], {%1,%2,%3,%4};"
                 :: "l"(p), "f"(a), "f"(b), "f"(c), "f"(d) : "memory");
}
__device__ __forceinline__ int ld_cg(const int* p) {
    int v; asm volatile("ld.global.cg.b32 %0, [%1];" : "=r"(v) : "l"(p) : "memory"); return v;
}

// ---------------- the single persistent kernel ----------------
__global__ void __launch_bounds__(NTHR, 1) k_fused(
        const float* __restrict__ inp, const void* __restrict__ dep,
        const void* __restrict__ ei,   const float* __restrict__ weight,
        const float* __restrict__ wcomp, const float* __restrict__ sw,
        const float* __restrict__ bias, float* __restrict__ out) {
    extern __shared__ float sm[];
    float* sW    = sm;                    // 129*132 = 17028 floats
    float* xsT   = sm + 17028;            // 129*132 = 17028 floats (transposed x)
    int*   s_src = (int*)(xsT + 17028);
    float* s_inv = (float*)(s_src + TROWS);
    int*   s_tgt = (int*)(s_inv + TROWS);
    int*   s_misc= (int*)(s_tgt + TROWS);

    const int bid = blockIdx.x, tid = threadIdx.x;
    const int gtid = bid*NTHR + tid, G = GRID*NTHR;
    const int wid = tid >> 5, lane = tid & 31;

    // ---- phase 0: zero scratch & output, reset flags, quick index-width sniff ----
    {
        const int4 z4 = make_int4(0,0,0,0);
        for (int k = gtid; k < NN*RR/4; k += G) ((int4*)g_comb)[k] = z4;
        const float4 f4 = make_float4(0.f,0.f,0.f,0.f);
        for (int k = gtid; k < NN*DD/4; k += G) ((float4*)out)[k] = f4;
        if (gtid < RR*8) g_cnt8[gtid] = 0;
        if (gtid == 0) { g_ticket = 0u; g_sdone = 0; g_bdone = 0; g_scan = 0; }
        if (bid == 0 && wid == 0) {       // 32-sample sniff: int64 iff all hi words 0
            const unsigned* eu = (const unsigned*)ei;
            unsigned any = (eu[2*lane + 1] != 0u) ? 1u : 0u;
            any = __ballot_sync(0xffffffffu, any);
            if (lane == 0) g_is64 = (any == 0u) ? 1 : 0;
        }
    }
    __threadfence();
    __syncthreads();
    if (tid == 0) {
        atomicAdd(&g_bar[0], 1);
        while (ld_cg(&g_bar[0]) < GRID) __nanosleep(32);
    }
    __syncthreads();

    // ---- fork: blocks 0..63 = edge chain; blocks 64..147 = basis expansion ----
    if (bid < 64) {
        const int e = bid*NTHR + tid;     // 64*256 = 16384 = NE
        int rel, sN, tN;
        if (g_is64) {
            rel = (int)((const long long*)dep)[e];
            sN  = (int)((const long long*)ei)[e];
            tN  = (int)((const long long*)ei)[NE + e];
        } else {
            rel = ((const int*)dep)[e];
            sN  = ((const int*)ei)[e];
            tN  = ((const int*)ei)[NE + e];
        }
        g_src[e] = sN; g_tgt[e] = tN;
        atomicAdd(&g_comb[tN*RR + rel], 1);
        const int bank = bid & 7;
        const int rk = atomicAdd(&g_cnt8[rel*8 + bank], 1);

        __threadfence();
        __syncthreads();
        if (tid == 0) atomicAdd(&g_bar[1], 1);

        if (bid == 0) {
            if (tid == 0) while (ld_cg(&g_bar[1]) < 64) __nanosleep(32);
            __syncthreads();
            if (tid < 32) {                       // parallel scan + tile list
                int vals[16], local = 0;
                #pragma unroll
                for (int k = 0; k < 16; k++) {
                    int c = g_cnt8[tid*16 + k];
                    vals[k] = local; local += c;
                }
                int x = local;
                #pragma unroll
                for (int d = 1; d < 32; d <<= 1) {
                    int y = __shfl_up_sync(0xffffffffu, x, d);
                    if (lane >= d) x += y;
                }
                const int excl = x - local;
                #pragma unroll
                for (int k = 0; k < 16; k++) g_off8[tid*16 + k] = excl + vals[k];
                const int r0 = 2*tid, r1 = 2*tid + 1;
                const int cnt0 = vals[8], cnt1 = local - vals[8];
                g_relcnt[r0] = cnt0; g_relcnt[r1] = cnt1;
                g_reloff[r0] = excl; g_reloff[r1] = excl + vals[8];
                const int nt0 = (cnt0 + TROWS-1)/TROWS, nt1 = (cnt1 + TROWS-1)/TROWS;
                const int ntl = nt0 + nt1;
                int ts = ntl;
                #pragma unroll
                for (int d = 1; d < 32; d <<= 1) {
                    int y = __shfl_up_sync(0xffffffffu, ts, d);
                    if (lane >= d) ts += y;
                }
                const int tbase = ts - ntl;
                for (int c = 0; c < nt0; c++) g_tiles[tbase + c] = (r0 << 8) | c;
                for (int c = 0; c < nt1; c++) g_tiles[tbase + nt0 + c] = (r1 << 8) | c;
                if (tid == 31) g_ntiles = ts;
            }
            __threadfence();
            __syncthreads();
            if (tid == 0) atomicExch(&g_scan, 1);
        } else {
            if (tid == 0) while (ld_cg(&g_scan) == 0) __nanosleep(32);
            __syncthreads();
        }
        g_sorted[g_off8[rel*8 + bank] + rk] = e;
        __threadfence();
        __syncthreads();
        if (tid == 0) atomicAdd(&g_sdone, 1);
    } else {
        // basis: 84 blocks over 128 i-planes (first 44 blocks take 2 planes)
        const int j = tid & 127, rh = tid >> 7;          // rh 0..1 -> 32 r's each
        for (int k = tid; k < RR*BB; k += NTHR) sm[k] = wcomp[k];
        __syncthreads();
        const int i1 = bid - 64;
        const int npass = (i1 < 44) ? 2 : 1;
        for (int ps = 0; ps < npass; ps++) {
            const int i = i1 + ps*84;
            float wr[BB];
            #pragma unroll
            for (int b = 0; b < BB; b++) wr[b] = weight[(b*DD + i)*DD + j];
            #pragma unroll 4
            for (int r = rh*32; r < rh*32 + 32; r++) {
                float a = 0.f;
                #pragma unroll
                for (int b = 0; b < BB; b++) a += sm[r*BB + b] * wr[b];
                g_fullW[((size_t)r*DD + i)*DD + j] = a;
            }
        }
        __threadfence();
        __syncthreads();
        if (tid == 0) atomicAdd(&g_bdone, 1);
    }

    // ---- ticket loop: self tiles (0..63) first, then gated edge tiles ----
    // thread tile: 8 rows x 8 cols; 256 threads = 16 tr x 16 tc -> 128x128 tile.
    // acc is f32x2 over ROW-PAIRS: acc[j][c] covers rows (8tr+2j, 8tr+2j+1), col 8tc+c.
    const int tr = tid >> 4;                   // 0..15: rows 8tr..8tr+7
    const int tc = tid & 15;                   // 0..15: cols 8tc..8tc+7
    const float* last_w = (const float*)0;
    bool edges_ok = false;
    int ntiles = 0;

    for (;;) {
        __syncthreads();                       // previous tile fully consumed
        if (tid == 0) s_misc[0] = (int)atomicAdd(&g_ticket, 1u);
        __syncthreads();
        const int t = s_misc[0];
        const bool is_self = (t < NN/TROWS);   // 64 self tiles

        int rel = 0, base, cnt, off = 0;
        if (is_self) { base = t*TROWS; cnt = NN; }
        else {
            if (!edges_ok) {                   // gate: scatter + basis complete
                if (tid == 0)
                    while (ld_cg(&g_sdone) < 64 || ld_cg(&g_bdone) < 84)
                        __nanosleep(64);
                __syncthreads();
                edges_ok = true;
                ntiles = g_ntiles;
            }
            if (t - NN/TROWS >= ntiles) break;
            const int tt = g_tiles[t - NN/TROWS];
            rel = tt >> 8; base = (tt & 255)*TROWS;
            cnt = g_relcnt[rel]; off = g_reloff[rel];
        }

        if (tid < TROWS) {                     // per-row metadata (128 rows)
            if (is_self) {
                s_src[tid] = base + tid; s_tgt[tid] = base + tid; s_inv[tid] = 1.f;
            } else {
                const int le = base + tid;
                const bool v = le < cnt;
                const int e = g_sorted[off + (v ? le : base)];
                const int sN = g_src[e], tN = g_tgt[e];
                s_src[tid] = sN; s_tgt[tid] = tN;
                s_inv[tid] = v ? 1.0f/(float)g_comb[tN*RR + rel] : 0.f;
            }
        }
        // stage W [128k x 128c] (stride WS), skipped when unchanged
        const float* wsrc = is_self ? sw : g_fullW + (size_t)rel*DD*DD;
        if (wsrc != last_w) {
            if (is_self) {                     // transpose sw on the fly
                #pragma unroll
                for (int p = 0; p < 16; p++) {
                    const int m = tid + p*NTHR;          // < 4096
                    const int jr = m & 127, k4 = m >> 7;
                    const float4 v = ((const float4*)sw)[jr*32 + k4];
                    sW[(4*k4 + 0)*WS + jr] = v.x;
                    sW[(4*k4 + 1)*WS + jr] = v.y;
                    sW[(4*k4 + 2)*WS + jr] = v.z;
                    sW[(4*k4 + 3)*WS + jr] = v.w;
                }
            } else {
                #pragma unroll
                for (int p = 0; p < 16; p++) {
                    const int m = tid + p*NTHR;          // < 4096
                    const int k = m >> 5, jj = m & 31;
                    ((float4*)sW)[k*33 + jj] = ((const float4*)wsrc)[m];
                }
            }
            last_w = wsrc;
        }
        __syncthreads();

        // gather x transposed, rowpair-packed: thread -> (rowpair, k-quarter)
        {
            const int rp = tid >> 2, q = tid & 3;        // rows 2rp,2rp+1; k q*32..
            const float4* ipa = (const float4*)(inp + (size_t)s_src[2*rp]*DD);
            const float4* ipb = (const float4*)(inp + (size_t)s_src[2*rp+1]*DD);
            #pragma unroll
            for (int i = 0; i < 8; i++) {
                const int k4 = q*8 + i;
                const float4 va = ipa[k4];
                const float4 vb = ipb[k4];
                float* b0 = xsT + (4*k4)*XT + 2*rp;
                asm volatile("st.shared.v2.f32 [%0], {%1,%2};" :: "l"(__cvta_generic_to_shared(b0)),        "f"(va.x), "f"(vb.x) : "memory");
                asm volatile("st.shared.v2.f32 [%0], {%1,%2};" :: "l"(__cvta_generic_to_shared(b0 + XT)),   "f"(va.y), "f"(vb.y) : "memory");
                asm volatile("st.shared.v2.f32 [%0], {%1,%2};" :: "l"(__cvta_generic_to_shared(b0 + 2*XT)), "f"(va.z), "f"(vb.z) : "memory");
                asm volatile("st.shared.v2.f32 [%0], {%1,%2};" :: "l"(__cvta_generic_to_shared(b0 + 3*XT)), "f"(va.w), "f"(vb.w) : "memory");
            }
        }
        __syncthreads();

        // warps whose 16 rows are all past cnt skip compute entirely
        if (is_self || base + 16*wid < cnt) {
            u64 acc[32];                       // [rowpair j 0..3][col c 0..7]
            #pragma unroll
            for (int q = 0; q < 32; q++) acc[q] = 0ull;

            const float* xp = xsT + 8*tr;      // 4 u64 per k (rowpairs), 16B aligned
            const float* wp = sW + 8*tc;       // 8 floats per k
            ulonglong2 xa = *(const ulonglong2*)xp;
            ulonglong2 xb = *(const ulonglong2*)(xp + 4);
            float4 wa = *(const float4*)wp;
            float4 wb = *(const float4*)(wp + 4);
            #pragma unroll 2
            for (int k = 0; k < DD; k++) {
                const ulonglong2 nxa = *(const ulonglong2*)(xp + (k+1)*XT);
                const ulonglong2 nxb = *(const ulonglong2*)(xp + (k+1)*XT + 4);
                const float4 nwa = *(const float4*)(wp + (k+1)*WS);
                const float4 nwb = *(const float4*)(wp + (k+1)*WS + 4);
                const u64 w0 = pack2(wa.x), w1 = pack2(wa.y);
                const u64 w2 = pack2(wa.z), w3 = pack2(wa.w);
                const u64 w4 = pack2(wb.x), w5 = pack2(wb.y);
                const u64 w6 = pack2(wb.z), w7 = pack2(wb.w);
                ffma2(acc[ 0], xa.x, w0); ffma2(acc[ 1], xa.x, w1);
                ffma2(acc[ 2], xa.x, w2); ffma2(acc[ 3], xa.x, w3);
                ffma2(acc[ 4], xa.x, w4); ffma2(acc[ 5], xa.x, w5);
                ffma2(acc[ 6], xa.x, w6); ffma2(acc[ 7], xa.x, w7);
                ffma2(acc[ 8], xa.y, w0); ffma2(acc[ 9], xa.y, w1);
                ffma2(acc[10], xa.y, w2); ffma2(acc[11], xa.y, w3);
                ffma2(acc[12], xa.y, w4); ffma2(acc[13], xa.y, w5);
                ffma2(acc[14], xa.y, w6); ffma2(acc[15], xa.y, w7);
                ffma2(acc[16], xb.x, w0); ffma2(acc[17], xb.x, w1);
                ffma2(acc[18], xb.x, w2); ffma2(acc[19], xb.x, w3);
                ffma2(acc[20], xb.x, w4); ffma2(acc[21], xb.x, w5);
                ffma2(acc[22], xb.x, w6); ffma2(acc[23], xb.x, w7);
                ffma2(acc[24], xb.y, w0); ffma2(acc[25], xb.y, w1);
                ffma2(acc[26], xb.y, w2); ffma2(acc[27], xb.y, w3);
                ffma2(acc[28], xb.y, w4); ffma2(acc[29], xb.y, w5);
                ffma2(acc[30], xb.y, w6); ffma2(acc[31], xb.y, w7);
                xa = nxa; xb = nxb; wa = nwa; wb = nwb;
            }

            // epilogue: per rowpair j, rows r0=8tr+2j (acc .x) and r0+1 (.y)
            float4 bb0 = make_float4(0.f,0.f,0.f,0.f);
            float4 bb1 = bb0;
            if (is_self) {
                bb0 = __ldg((const float4*)bias + 2*tc);
                bb1 = __ldg((const float4*)bias + 2*tc + 1);
            }
            #pragma unroll
            for (int j = 0; j < 4; j++) {
                const int r0 = 8*tr + 2*j;
                const float2 c0 = unpack2(acc[8*j + 0]);
                const float2 c1 = unpack2(acc[8*j + 1]);
                const float2 c2 = unpack2(acc[8*j + 2]);
                const float2 c3 = unpack2(acc[8*j + 3]);
                const float2 c4 = unpack2(acc[8*j + 4]);
                const float2 c5 = unpack2(acc[8*j + 5]);
                const float2 c6 = unpack2(acc[8*j + 6]);
                const float2 c7 = unpack2(acc[8*j + 7]);
                const float i0 = s_inv[r0], i1 = s_inv[r0 + 1];
                if (i0 != 0.f) {
                    float* op = out + (size_t)s_tgt[r0]*DD + 8*tc;
                    red4(op,     c0.x*i0 + bb0.x, c1.x*i0 + bb0.y,
                                 c2.x*i0 + bb0.z, c3.x*i0 + bb0.w);
                    red4(op + 4, c4.x*i0 + bb1.x, c5.x*i0 + bb1.y,
                                 c6.x*i0 + bb1.z, c7.x*i0 + bb1.w);
                }
                if (i1 != 0.f) {
                    float* op = out + (size_t)s_tgt[r0 + 1]*DD + 8*tc;
                    red4(op,     c0.y*i1 + bb0.x, c1.y*i1 + bb0.y,
                                 c2.y*i1 + bb0.z, c3.y*i1 + bb0.w);
                    red4(op + 4, c4.y*i1 + bb1.x, c5.y*i1 + bb1.y,
                                 c6.y*i1 + bb1.z, c7.y*i1 + bb1.w);
                }
            }
        }
    }

    // ---- epilogue: last block resets barrier slots for graph replay ----
    __threadfence();
    __syncthreads();
    if (tid == 0) {
        const int done = atomicAdd(&g_bar[7], 1);
        if (done == GRID - 1) {
            #pragma unroll
            for (int p = 0; p < 8; p++) g_bar[p] = 0;
            __threadfence();
        }
    }
}

// ---------------- launch ----------------
extern "C" void kernel_launch(void* const* d_in, const int* in_sizes, int n_in,
                              void* d_out, int out_size) {
    const float* inp    = (const float*)d_in[0];
    const void*  dep    = d_in[1];
    const void*  ei     = d_in[2];
    const float* weight = (const float*)d_in[3];
    const float* wcomp  = (const float*)d_in[4];
    const float* sw     = (const float*)d_in[5];
    const float* bias   = (const float*)d_in[6];
    float* out = (float*)d_out;

    const int SMEM = (17028 + 17028 + TROWS*3 + 8) * 4;   // ~134.8 KB
    cudaFuncSetAttribute(k_fused, cudaFuncAttributeMaxDynamicSharedMemorySize, SMEM);

    k_fused<<<GRID, NTHR, SMEM>>>(inp, dep, ei, weight, wcomp, sw, bias, out);
}

// round 11
// speedup vs baseline: 1.1904x; 1.1262x over previous
#include <cuda_runtime.h>

#define NN 8192
#define NE 16384
#define DD 128
#define RR 64
#define BB 16
#define GRID 296            // 2 blocks per SM, all co-resident
#define NTHR 256
#define TROWS 64            // rows per tile
#define WS 132              // sW k-row stride in words
#define XT 68               // xsT k-row stride in words (32 rowpairs + 2 pad, u64)

typedef unsigned long long u64;

// ---------------- device scratch (no allocations allowed) ----------------
__device__ __align__(16) float g_fullW[RR*DD*DD];   // 4 MB expanded basis
__device__ int g_comb[NN*RR];                       // (tgt,rel) bucket counts
__device__ int g_cnt8[RR*8];                        // banked relation counters
__device__ int g_off8[RR*8];                        // scanned bank offsets
__device__ int g_relcnt[RR], g_reloff[RR];
__device__ int g_src[NE], g_tgt[NE];
__device__ int g_sorted[NE];
__device__ int g_tiles[1024], g_ntiles;
__device__ int g_is64;
__device__ int g_bar[8];
__device__ int g_sdone, g_bdone, g_scan;
__device__ unsigned g_ticket;

// ---------------- helpers ----------------
__device__ __forceinline__ u64 pack2(float x) {
    u64 r; asm("mov.b64 %0, {%1, %1};" : "=l"(r) : "f"(x)); return r;
}
__device__ __forceinline__ void ffma2(u64& d, u64 a, u64 b) {
    asm("fma.rn.f32x2 %0, %1, %2, %0;" : "+l"(d) : "l"(a), "l"(b));
}
__device__ __forceinline__ float2 unpack2(u64 v) {
    float2 f; asm("mov.b64 {%0, %1}, %2;" : "=f"(f.x), "=f"(f.y) : "l"(v)); return f;
}
__device__ __forceinline__ void red4(float* p, float a, float b, float c, float d) {
    asm volatile("red.global.add.v4.f32 [%0], {%1,%2,%3,%4};"
                 :: "l"(p), "f"(a), "f"(b), "f"(c), "f"(d) : "memory");
}
__device__ __forceinline__ int ld_cg(const int* p) {
    int v; asm volatile("ld.global.cg.b32 %0, [%1];" : "=r"(v) : "l"(p) : "memory"); return v;
}

// ---------------- the single persistent kernel ----------------
__global__ void __launch_bounds__(NTHR, 2) k_fused(
        const float* __restrict__ inp, const void* __restrict__ dep,
        const void* __restrict__ ei,   const float* __restrict__ weight,
        const float* __restrict__ wcomp, const float* __restrict__ sw,
        const float* __restrict__ bias, float* __restrict__ out) {
    extern __shared__ float sm[];
    float* sW    = sm;                    // 129*132 = 17028 floats
    float* xsT   = sm + 17028;            // 129*68  =  8772 floats (rowpair-packed x)
    int*   s_src = (int*)(xsT + 8772);
    float* s_inv = (float*)(s_src + TROWS);
    int*   s_tgt = (int*)(s_inv + TROWS);
    int*   s_misc= (int*)(s_tgt + TROWS);

    const int bid = blockIdx.x, tid = threadIdx.x;
    const int gtid = bid*NTHR + tid, G = GRID*NTHR;
    const int wid = tid >> 5, lane = tid & 31;

    // ---- phase 0: zero scratch & output, reset flags, quick index-width sniff ----
    {
        const int4 z4 = make_int4(0,0,0,0);
        for (int k = gtid; k < NN*RR/4; k += G) ((int4*)g_comb)[k] = z4;
        const float4 f4 = make_float4(0.f,0.f,0.f,0.f);
        for (int k = gtid; k < NN*DD/4; k += G) ((float4*)out)[k] = f4;
        if (gtid < RR*8) g_cnt8[gtid] = 0;
        if (gtid == 0) { g_ticket = 0u; g_sdone = 0; g_bdone = 0; g_scan = 0; }
        if (bid == 0 && wid == 0) {       // 32-sample sniff: int64 iff all hi words 0
            const unsigned* eu = (const unsigned*)ei;
            unsigned any = (eu[2*lane + 1] != 0u) ? 1u : 0u;
            any = __ballot_sync(0xffffffffu, any);
            if (lane == 0) g_is64 = (any == 0u) ? 1 : 0;
        }
    }
    __threadfence();
    __syncthreads();
    if (tid == 0) {
        atomicAdd(&g_bar[0], 1);
        while (ld_cg(&g_bar[0]) < GRID) __nanosleep(32);
    }
    __syncthreads();

    // ---- fork: blocks 0..63 = edge chain; 64..147 = basis; 148+ = straight to tiles ----
    if (bid < 64) {
        const int e = bid*NTHR + tid;     // 64*256 = 16384 = NE
        int rel, sN, tN;
        if (g_is64) {
            rel = (int)((const long long*)dep)[e];
            sN  = (int)((const long long*)ei)[e];
            tN  = (int)((const long long*)ei)[NE + e];
        } else {
            rel = ((const int*)dep)[e];
            sN  = ((const int*)ei)[e];
            tN  = ((const int*)ei)[NE + e];
        }
        g_src[e] = sN; g_tgt[e] = tN;
        atomicAdd(&g_comb[tN*RR + rel], 1);
        const int bank = bid & 7;
        const int rk = atomicAdd(&g_cnt8[rel*8 + bank], 1);

        __threadfence();
        __syncthreads();
        if (tid == 0) atomicAdd(&g_bar[1], 1);

        if (bid == 0) {
            if (tid == 0) while (ld_cg(&g_bar[1]) < 64) __nanosleep(32);
            __syncthreads();
            if (tid < 32) {                       // parallel scan + tile list
                int vals[16], local = 0;
                #pragma unroll
                for (int k = 0; k < 16; k++) {
                    int c = g_cnt8[tid*16 + k];
                    vals[k] = local; local += c;
                }
                int x = local;
                #pragma unroll
                for (int d = 1; d < 32; d <<= 1) {
                    int y = __shfl_up_sync(0xffffffffu, x, d);
                    if (lane >= d) x += y;
                }
                const int excl = x - local;
                #pragma unroll
                for (int k = 0; k < 16; k++) g_off8[tid*16 + k] = excl + vals[k];
                const int r0 = 2*tid, r1 = 2*tid + 1;
                const int cnt0 = vals[8], cnt1 = local - vals[8];
                g_relcnt[r0] = cnt0; g_relcnt[r1] = cnt1;
                g_reloff[r0] = excl; g_reloff[r1] = excl + vals[8];
                const int nt0 = (cnt0 + TROWS-1)/TROWS, nt1 = (cnt1 + TROWS-1)/TROWS;
                const int ntl = nt0 + nt1;
                int ts = ntl;
                #pragma unroll
                for (int d = 1; d < 32; d <<= 1) {
                    int y = __shfl_up_sync(0xffffffffu, ts, d);
                    if (lane >= d) ts += y;
                }
                const int tbase = ts - ntl;
                for (int c = 0; c < nt0; c++) g_tiles[tbase + c] = (r0 << 8) | c;
                for (int c = 0; c < nt1; c++) g_tiles[tbase + nt0 + c] = (r1 << 8) | c;
                if (tid == 31) g_ntiles = ts;
            }
            __threadfence();
            __syncthreads();
            if (tid == 0) atomicExch(&g_scan, 1);
        } else {
            if (tid == 0) while (ld_cg(&g_scan) == 0) __nanosleep(32);
            __syncthreads();
        }
        g_sorted[g_off8[rel*8 + bank] + rk] = e;
        __threadfence();
        __syncthreads();
        if (tid == 0) atomicAdd(&g_sdone, 1);
    } else if (bid < 148) {
        // basis: 84 blocks over 128 i-planes (first 44 blocks take 2 planes)
        const int j = tid & 127, rh = tid >> 7;          // rh 0..1 -> 32 r's each
        for (int k = tid; k < RR*BB; k += NTHR) sm[k] = wcomp[k];
        __syncthreads();
        const int i1 = bid - 64;
        const int npass = (i1 < 44) ? 2 : 1;
        for (int ps = 0; ps < npass; ps++) {
            const int i = i1 + ps*84;
            float wr[BB];
            #pragma unroll
            for (int b = 0; b < BB; b++) wr[b] = weight[(b*DD + i)*DD + j];
            #pragma unroll 4
            for (int r = rh*32; r < rh*32 + 32; r++) {
                float a = 0.f;
                #pragma unroll
                for (int b = 0; b < BB; b++) a += sm[r*BB + b] * wr[b];
                g_fullW[((size_t)r*DD + i)*DD + j] = a;
            }
        }
        __threadfence();
        __syncthreads();
        if (tid == 0) atomicAdd(&g_bdone, 1);
    }

    // ---- ticket loop: self tiles (0..127) first, then gated edge tiles ----
    // thread tile: 8 rows x 4 cols; 256 threads = 8 tr x 32 tc -> 64x128 tile.
    // acc is f32x2 over ROW-PAIRS: acc[rp][c] covers rows (8tr+2rp, 8tr+2rp+1).
    const int tr = wid;                        // 0..7: rows 8tr..8tr+7 (warp-uniform)
    const int tc = lane;                       // 0..31: cols 4tc..4tc+3
    const float* last_w = (const float*)0;
    bool edges_ok = false;
    int ntiles = 0;

    for (;;) {
        __syncthreads();                       // previous tile fully consumed
        if (tid == 0) s_misc[0] = (int)atomicAdd(&g_ticket, 1u);
        __syncthreads();
        const int t = s_misc[0];
        const bool is_self = (t < NN/TROWS);   // 128 self tiles

        int rel = 0, base, cnt, off = 0;
        if (is_self) { base = t*TROWS; cnt = NN; }
        else {
            if (!edges_ok) {                   // gate: scatter + basis complete
                if (tid == 0)
                    while (ld_cg(&g_sdone) < 64 || ld_cg(&g_bdone) < 84)
                        __nanosleep(64);
                __syncthreads();
                edges_ok = true;
                ntiles = g_ntiles;
            }
            if (t - NN/TROWS >= ntiles) break;
            const int tt = g_tiles[t - NN/TROWS];
            rel = tt >> 8; base = (tt & 255)*TROWS;
            cnt = g_relcnt[rel]; off = g_reloff[rel];
        }

        if (tid < TROWS) {                     // per-row metadata (64 rows)
            if (is_self) {
                s_src[tid] = base + tid; s_tgt[tid] = base + tid; s_inv[tid] = 1.f;
            } else {
                const int le = base + tid;
                const bool v = le < cnt;
                const int e = g_sorted[off + (v ? le : base)];
                const int sN = g_src[e], tN = g_tgt[e];
                s_src[tid] = sN; s_tgt[tid] = tN;
                s_inv[tid] = v ? 1.0f/(float)g_comb[tN*RR + rel] : 0.f;
            }
        }
        // stage W [128k x 128c] (stride WS), skipped when unchanged
        const float* wsrc = is_self ? sw : g_fullW + (size_t)rel*DD*DD;
        if (wsrc != last_w) {
            if (is_self) {                     // transpose sw on the fly
                #pragma unroll
                for (int p = 0; p < 16; p++) {
                    const int m = tid + p*NTHR;          // < 4096
                    const int jr = m & 127, k4 = m >> 7;
                    const float4 v = ((const float4*)sw)[jr*32 + k4];
                    sW[(4*k4 + 0)*WS + jr] = v.x;
                    sW[(4*k4 + 1)*WS + jr] = v.y;
                    sW[(4*k4 + 2)*WS + jr] = v.z;
                    sW[(4*k4 + 3)*WS + jr] = v.w;
                }
            } else {
                #pragma unroll
                for (int p = 0; p < 16; p++) {
                    const int m = tid + p*NTHR;          // < 4096
                    const int k = m >> 5, jj = m & 31;
                    ((float4*)sW)[k*33 + jj] = ((const float4*)wsrc)[m];
                }
            }
            last_w = wsrc;
        }
        __syncthreads();

        // gather x transposed, rowpair-packed: thread -> (rowpair, k-eighth)
        {
            const int rp = tid >> 3, q = tid & 7;        // rows 2rp,2rp+1; k q*16..
            const float4* ipa = (const float4*)(inp + (size_t)s_src[2*rp]*DD);
            const float4* ipb = (const float4*)(inp + (size_t)s_src[2*rp+1]*DD);
            #pragma unroll
            for (int i = 0; i < 4; i++) {
                const int k4 = q*4 + i;
                const float4 va = ipa[k4];
                const float4 vb = ipb[k4];
                float* b0 = xsT + (4*k4)*XT + 2*rp;
                asm volatile("st.shared.v2.f32 [%0], {%1,%2};" :: "l"(__cvta_generic_to_shared(b0)),        "f"(va.x), "f"(vb.x) : "memory");
                asm volatile("st.shared.v2.f32 [%0], {%1,%2};" :: "l"(__cvta_generic_to_shared(b0 + XT)),   "f"(va.y), "f"(vb.y) : "memory");
                asm volatile("st.shared.v2.f32 [%0], {%1,%2};" :: "l"(__cvta_generic_to_shared(b0 + 2*XT)), "f"(va.z), "f"(vb.z) : "memory");
                asm volatile("st.shared.v2.f32 [%0], {%1,%2};" :: "l"(__cvta_generic_to_shared(b0 + 3*XT)), "f"(va.w), "f"(vb.w) : "memory");
            }
        }
        __syncthreads();

        // warps whose 8 rows are all past cnt skip compute entirely
        if (is_self || base + 8*wid < cnt) {
            u64 acc[16];                       // [rowpair rp 0..3][col c 0..3]
            #pragma unroll
            for (int q = 0; q < 16; q++) acc[q] = 0ull;

            const float* xp = xsT + 8*tr;      // 4 u64 per k (broadcast), 16B aligned
            const float* wp = sW + 4*tc;       // 4 floats per k (coalesced 512B)
            ulonglong2 xa = *(const ulonglong2*)xp;
            ulonglong2 xb = *(const ulonglong2*)(xp + 4);
            float4 wv = *(const float4*)wp;
            #pragma unroll 4
            for (int k = 0; k < DD; k++) {
                const ulonglong2 nxa = *(const ulonglong2*)(xp + (k+1)*XT);
                const ulonglong2 nxb = *(const ulonglong2*)(xp + (k+1)*XT + 4);
                const float4 nwv = *(const float4*)(wp + (k+1)*WS);
                const u64 w0 = pack2(wv.x), w1 = pack2(wv.y);
                const u64 w2 = pack2(wv.z), w3 = pack2(wv.w);
                ffma2(acc[ 0], xa.x, w0); ffma2(acc[ 1], xa.x, w1);
                ffma2(acc[ 2], xa.x, w2); ffma2(acc[ 3], xa.x, w3);
                ffma2(acc[ 4], xa.y, w0); ffma2(acc[ 5], xa.y, w1);
                ffma2(acc[ 6], xa.y, w2); ffma2(acc[ 7], xa.y, w3);
                ffma2(acc[ 8], xb.x, w0); ffma2(acc[ 9], xb.x, w1);
                ffma2(acc[10], xb.x, w2); ffma2(acc[11], xb.x, w3);
                ffma2(acc[12], xb.y, w0); ffma2(acc[13], xb.y, w1);
                ffma2(acc[14], xb.y, w2); ffma2(acc[15], xb.y, w3);
                xa = nxa; xb = nxb; wv = nwv;
            }

            // epilogue: per rowpair rp, rows r0 (acc .x) and r0+1 (.y), 4 cols
            float4 bb = make_float4(0.f,0.f,0.f,0.f);
            if (is_self) bb = __ldg((const float4*)bias + tc);
            #pragma unroll
            for (int rp = 0; rp < 4; rp++) {
                const int r0 = 8*tr + 2*rp;
                const float2 c0 = unpack2(acc[4*rp + 0]);
                const float2 c1 = unpack2(acc[4*rp + 1]);
                const float2 c2 = unpack2(acc[4*rp + 2]);
                const float2 c3 = unpack2(acc[4*rp + 3]);
                const float i0 = s_inv[r0], i1 = s_inv[r0 + 1];
                if (i0 != 0.f)
                    red4(out + (size_t)s_tgt[r0]*DD + 4*tc,
                         c0.x*i0 + bb.x, c1.x*i0 + bb.y,
                         c2.x*i0 + bb.z, c3.x*i0 + bb.w);
                if (i1 != 0.f)
                    red4(out + (size_t)s_tgt[r0 + 1]*DD + 4*tc,
                         c0.y*i1 + bb.x, c1.y*i1 + bb.y,
                         c2.y*i1 + bb.z, c3.y*i1 + bb.w);
            }
        }
    }

    // ---- epilogue: last block resets barrier slots for graph replay ----
    __threadfence();
    __syncthreads();
    if (tid == 0) {
        const int done = atomicAdd(&g_bar[7], 1);
        if (done == GRID - 1) {
            #pragma unroll
            for (int p = 0; p < 8; p++) g_bar[p] = 0;
            __threadfence();
        }
    }
}

// ---------------- launch ----------------
extern "C" void kernel_launch(void* const* d_in, const int* in_sizes, int n_in,
                              void* d_out, int out_size) {
    const float* inp    = (const float*)d_in[0];
    const void*  dep    = d_in[1];
    const void*  ei     = d_in[2];
    const float* weight = (const float*)d_in[3];
    const float* wcomp  = (const float*)d_in[4];
    const float* sw     = (const float*)d_in[5];
    const float* bias   = (const float*)d_in[6];
    float* out = (float*)d_out;

    const int SMEM = (17028 + 8772 + TROWS*3 + 8) * 4;   // ~101.6 KB -> 2 blocks/SM
    cudaFuncSetAttribute(k_fused, cudaFuncAttributeMaxDynamicSharedMemorySize, SMEM);

    k_fused<<<GRID, NTHR, SMEM>>>(inp, dep, ei, weight, wcomp, sw, bias, out);
}

// round 12
// speedup vs baseline: 1.3025x; 1.0941x over previous
#include <cuda_runtime.h>

#define NN 8192
#define NE 16384
#define DD 128
#define RR 64
#define BB 16
#define GRID 296            // 2 blocks per SM, all co-resident
#define NTHR 256
#define TROWS 64            // rows per tile
#define WS 128              // sW k-row stride (dense, cp.async-friendly)
#define XT 64               // xsT k-row stride (dense, rowpair-packed)

typedef unsigned long long u64;

// ---------------- device scratch (no allocations allowed) ----------------
__device__ __align__(16) float g_fullW[RR*DD*DD];   // 4 MB expanded basis
__device__ int g_comb[NN*RR];                       // (tgt,rel) bucket counts
__device__ int g_cnt8[RR*8];                        // banked relation counters
__device__ int g_off8[RR*8];                        // scanned bank offsets
__device__ int g_relcnt[RR], g_reloff[RR];
__device__ int g_src[NE], g_tgt[NE];
__device__ int g_sorted[NE];
__device__ int g_tiles[1024], g_ntiles;
__device__ int g_is64;
__device__ int g_bar[8];
__device__ int g_sdone, g_bdone, g_scan;
__device__ unsigned g_ticket;

// ---------------- helpers ----------------
__device__ __forceinline__ u64 pack2(float x) {
    u64 r; asm("mov.b64 %0, {%1, %1};" : "=l"(r) : "f"(x)); return r;
}
__device__ __forceinline__ void ffma2(u64& d, u64 a, u64 b) {
    asm("fma.rn.f32x2 %0, %1, %2, %0;" : "+l"(d) : "l"(a), "l"(b));
}
__device__ __forceinline__ float2 unpack2(u64 v) {
    float2 f; asm("mov.b64 {%0, %1}, %2;" : "=f"(f.x), "=f"(f.y) : "l"(v)); return f;
}
__device__ __forceinline__ void red4(float* p, float a, float b, float c, float d) {
    asm volatile("red.global.add.v4.f32 [%0], {%1,%2,%3,%4};"
                 :: "l"(p), "f"(a), "f"(b), "f"(c), "f"(d) : "memory");
}
__device__ __forceinline__ int ld_cg(const int* p) {
    int v; asm volatile("ld.global.cg.b32 %0, [%1];" : "=r"(v) : "l"(p) : "memory"); return v;
}
__device__ __forceinline__ void cpasync16(unsigned dst, const void* src) {
    asm volatile("cp.async.cg.shared.global [%0], [%1], 16;" :: "r"(dst), "l"(src) : "memory");
}
__device__ __forceinline__ void sts2(float* p, float a, float b) {
    asm volatile("st.shared.v2.f32 [%0], {%1,%2};"
                 :: "l"(__cvta_generic_to_shared(p)), "f"(a), "f"(b) : "memory");
}

// ---------------- the single persistent kernel ----------------
__global__ void __launch_bounds__(NTHR, 2) k_fused(
        const float* __restrict__ inp, const void* __restrict__ dep,
        const void* __restrict__ ei,   const float* __restrict__ weight,
        const float* __restrict__ wcomp, const float* __restrict__ sw,
        const float* __restrict__ bias, float* __restrict__ out) {
    extern __shared__ float sm[];
    float* sW    = sm;                    // 129*128 = 16512 floats (row 128 = prefetch pad)
    float* xsT   = sm + 16512;            // 129*64  =  8256 floats (rowpair-packed x)
    int*   s_tgt = (int*)(xsT + 8256);
    int*   s_misc= (int*)(s_tgt + TROWS);

    const int bid = blockIdx.x, tid = threadIdx.x;
    const int gtid = bid*NTHR + tid, G = GRID*NTHR;
    const int wid = tid >> 5, lane = tid & 31;

    // ---- phase 0: zero scratch & output, reset flags, quick index-width sniff ----
    {
        const int4 z4 = make_int4(0,0,0,0);
        for (int k = gtid; k < NN*RR/4; k += G) ((int4*)g_comb)[k] = z4;
        const float4 f4 = make_float4(0.f,0.f,0.f,0.f);
        for (int k = gtid; k < NN*DD/4; k += G) ((float4*)out)[k] = f4;
        if (gtid < RR*8) g_cnt8[gtid] = 0;
        if (gtid == 0) { g_ticket = 0u; g_sdone = 0; g_bdone = 0; g_scan = 0; }
        if (bid == 0 && wid == 0) {       // 32-sample sniff: int64 iff all hi words 0
            const unsigned* eu = (const unsigned*)ei;
            unsigned any = (eu[2*lane + 1] != 0u) ? 1u : 0u;
            any = __ballot_sync(0xffffffffu, any);
            if (lane == 0) g_is64 = (any == 0u) ? 1 : 0;
        }
    }
    __threadfence();
    __syncthreads();
    if (tid == 0) {
        atomicAdd(&g_bar[0], 1);
        while (ld_cg(&g_bar[0]) < GRID) __nanosleep(32);
    }
    __syncthreads();

    // ---- fork: blocks 0..63 = edge chain; 64..147 = basis; 148+ = straight to tiles ----
    if (bid < 64) {
        const int e = bid*NTHR + tid;     // 64*256 = 16384 = NE
        int rel, sN, tN;
        if (g_is64) {
            rel = (int)((const long long*)dep)[e];
            sN  = (int)((const long long*)ei)[e];
            tN  = (int)((const long long*)ei)[NE + e];
        } else {
            rel = ((const int*)dep)[e];
            sN  = ((const int*)ei)[e];
            tN  = ((const int*)ei)[NE + e];
        }
        g_src[e] = sN; g_tgt[e] = tN;
        atomicAdd(&g_comb[tN*RR + rel], 1);
        const int bank = bid & 7;
        const int rk = atomicAdd(&g_cnt8[rel*8 + bank], 1);

        __threadfence();
        __syncthreads();
        if (tid == 0) atomicAdd(&g_bar[1], 1);

        if (bid == 0) {
            if (tid == 0) while (ld_cg(&g_bar[1]) < 64) __nanosleep(32);
            __syncthreads();
            if (tid < 32) {                       // parallel scan + tile list
                int vals[16], local = 0;
                #pragma unroll
                for (int k = 0; k < 16; k++) {
                    int c = g_cnt8[tid*16 + k];
                    vals[k] = local; local += c;
                }
                int x = local;
                #pragma unroll
                for (int d = 1; d < 32; d <<= 1) {
                    int y = __shfl_up_sync(0xffffffffu, x, d);
                    if (lane >= d) x += y;
                }
                const int excl = x - local;
                #pragma unroll
                for (int k = 0; k < 16; k++) g_off8[tid*16 + k] = excl + vals[k];
                const int r0 = 2*tid, r1 = 2*tid + 1;
                const int cnt0 = vals[8], cnt1 = local - vals[8];
                g_relcnt[r0] = cnt0; g_relcnt[r1] = cnt1;
                g_reloff[r0] = excl; g_reloff[r1] = excl + vals[8];
                const int nt0 = (cnt0 + TROWS-1)/TROWS, nt1 = (cnt1 + TROWS-1)/TROWS;
                const int ntl = nt0 + nt1;
                int ts = ntl;
                #pragma unroll
                for (int d = 1; d < 32; d <<= 1) {
                    int y = __shfl_up_sync(0xffffffffu, ts, d);
                    if (lane >= d) ts += y;
                }
                const int tbase = ts - ntl;
                for (int c = 0; c < nt0; c++) g_tiles[tbase + c] = (r0 << 8) | c;
                for (int c = 0; c < nt1; c++) g_tiles[tbase + nt0 + c] = (r1 << 8) | c;
                if (tid == 31) g_ntiles = ts;
            }
            __threadfence();
            __syncthreads();
            if (tid == 0) atomicExch(&g_scan, 1);
        } else {
            if (tid == 0) while (ld_cg(&g_scan) == 0) __nanosleep(32);
            __syncthreads();
        }
        g_sorted[g_off8[rel*8 + bank] + rk] = e;
        __threadfence();
        __syncthreads();
        if (tid == 0) atomicAdd(&g_sdone, 1);
    } else if (bid < 148) {
        // basis: 84 blocks over 128 i-planes (first 44 blocks take 2 planes)
        const int j = tid & 127, rh = tid >> 7;          // rh 0..1 -> 32 r's each
        for (int k = tid; k < RR*BB; k += NTHR) sm[k] = wcomp[k];
        __syncthreads();
        const int i1 = bid - 64;
        const int npass = (i1 < 44) ? 2 : 1;
        for (int ps = 0; ps < npass; ps++) {
            const int i = i1 + ps*84;
            float wr[BB];
            #pragma unroll
            for (int b = 0; b < BB; b++) wr[b] = weight[(b*DD + i)*DD + j];
            #pragma unroll 4
            for (int r = rh*32; r < rh*32 + 32; r++) {
                float a = 0.f;
                #pragma unroll
                for (int b = 0; b < BB; b++) a += sm[r*BB + b] * wr[b];
                g_fullW[((size_t)r*DD + i)*DD + j] = a;
            }
        }
        __threadfence();
        __syncthreads();
        if (tid == 0) atomicAdd(&g_bdone, 1);
    }

    // ---- ticket loop: self tiles (0..127) first, then gated edge tiles ----
    // thread tile: 8 rows x 4 cols; 256 threads = 8 tr x 32 tc -> 64x128 tile.
    // acc = f32x2 over ROW-PAIRS; x rows pre-scaled by 1/count during gather.
    const int tr = wid;                        // 0..7: rows 8tr..8tr+7 (warp-uniform)
    const int tc = lane;                       // 0..31: cols 4tc..4tc+3
    const unsigned sW_u32 = (unsigned)__cvta_generic_to_shared(sW);
    const float* last_w = (const float*)0;
    bool edges_ok = false;
    int ntiles = 0;

    for (;;) {
        __syncthreads();                       // previous tile fully consumed
        if (tid == 0) s_misc[0] = (int)atomicAdd(&g_ticket, 1u);
        __syncthreads();
        const int t = s_misc[0];
        const bool is_self = (t < NN/TROWS);   // 128 self tiles

        int rel = 0, base, cnt, off = 0;
        if (is_self) { base = t*TROWS; cnt = NN; }
        else {
            if (!edges_ok) {                   // gate: scatter + basis complete
                if (tid == 0)
                    while (ld_cg(&g_sdone) < 64 || ld_cg(&g_bdone) < 84)
                        __nanosleep(64);
                __syncthreads();
                edges_ok = true;
                ntiles = g_ntiles;
            }
            if (t - NN/TROWS >= ntiles) break;
            const int tt = g_tiles[t - NN/TROWS];
            rel = tt >> 8; base = (tt & 255)*TROWS;
            cnt = g_relcnt[rel]; off = g_reloff[rel];
        }

        // ---- stage W (async for edges), overlapped with the x-gather below ----
        const float* wsrc = is_self ? sw : g_fullW + (size_t)rel*DD*DD;
        if (wsrc != last_w) {
            if (is_self) {                     // transpose sw on the fly (sync STS)
                #pragma unroll
                for (int p = 0; p < 16; p++) {
                    const int m = tid + p*NTHR;          // < 4096
                    const int jr = m & 127, k4 = m >> 7;
                    const float4 v = ((const float4*)sw)[jr*32 + k4];
                    sW[(4*k4 + 0)*WS + jr] = v.x;
                    sW[(4*k4 + 1)*WS + jr] = v.y;
                    sW[(4*k4 + 2)*WS + jr] = v.z;
                    sW[(4*k4 + 3)*WS + jr] = v.w;
                }
            } else {                           // dense 64KB copy via cp.async
                const float4* src4 = (const float4*)wsrc + tid;
                const unsigned d0 = sW_u32 + tid*16;
                #pragma unroll
                for (int p = 0; p < 16; p++)
                    cpasync16(d0 + p*4096, src4 + p*256);
                asm volatile("cp.async.commit_group;" ::: "memory");
            }
            last_w = wsrc;
        }

        // ---- gather x (rowpair-packed, pre-scaled), inline src/inv lookup ----
        {
            const int rp = lane, q = wid;      // rows 2rp,2rp+1; k-chunk 16q..16q+15
            int s0, s1; float inv0, inv1;
            if (is_self) {
                s0 = base + 2*rp; s1 = s0 + 1; inv0 = 1.f; inv1 = 1.f;
                if (q == 0) { s_tgt[2*rp] = s0; s_tgt[2*rp + 1] = s1; }
            } else {
                const int le0 = base + 2*rp, le1 = le0 + 1;
                const int e0 = g_sorted[off + (le0 < cnt ? le0 : base)];
                const int e1 = g_sorted[off + (le1 < cnt ? le1 : base)];
                s0 = g_src[e0]; s1 = g_src[e1];
                const int t0 = g_tgt[e0], t1 = g_tgt[e1];
                inv0 = (le0 < cnt) ? 1.0f/(float)g_comb[t0*RR + rel] : 0.f;
                inv1 = (le1 < cnt) ? 1.0f/(float)g_comb[t1*RR + rel] : 0.f;
                if (q == 0) { s_tgt[2*rp] = t0; s_tgt[2*rp + 1] = t1; }
            }
            const float4* ipa = (const float4*)(inp + (size_t)s0*DD);
            const float4* ipb = (const float4*)(inp + (size_t)s1*DD);
            #pragma unroll
            for (int i = 0; i < 4; i++) {
                const int k4 = 4*q + i;
                const float4 va = ipa[k4];
                const float4 vb = ipb[k4];
                float* b0 = xsT + (4*k4)*XT + 2*rp;
                sts2(b0,        va.x*inv0, vb.x*inv1);
                sts2(b0 + XT,   va.y*inv0, vb.y*inv1);
                sts2(b0 + 2*XT, va.z*inv0, vb.z*inv1);
                sts2(b0 + 3*XT, va.w*inv0, vb.w*inv1);
            }
        }
        asm volatile("cp.async.wait_group 0;" ::: "memory");
        __syncthreads();

        // warps whose 8 rows are all past cnt skip compute entirely
        if (is_self || base + 8*tr < cnt) {
            u64 acc[16];                       // [rowpair rp 0..3][col c 0..3]
            #pragma unroll
            for (int q = 0; q < 16; q++) acc[q] = 0ull;

            const float* xp = xsT + 8*tr;      // 4 u64 per k (broadcast), 16B aligned
            const float* wp = sW + 4*tc;       // 4 floats per k (coalesced 512B)
            ulonglong2 xa = *(const ulonglong2*)xp;
            ulonglong2 xb = *(const ulonglong2*)(xp + 4);
            float4 wv = *(const float4*)wp;
            #pragma unroll 4
            for (int k = 0; k < DD; k++) {
                const ulonglong2 nxa = *(const ulonglong2*)(xp + (k+1)*XT);
                const ulonglong2 nxb = *(const ulonglong2*)(xp + (k+1)*XT + 4);
                const float4 nwv = *(const float4*)(wp + (k+1)*WS);
                const u64 w0 = pack2(wv.x), w1 = pack2(wv.y);
                const u64 w2 = pack2(wv.z), w3 = pack2(wv.w);
                ffma2(acc[ 0], xa.x, w0); ffma2(acc[ 1], xa.x, w1);
                ffma2(acc[ 2], xa.x, w2); ffma2(acc[ 3], xa.x, w3);
                ffma2(acc[ 4], xa.y, w0); ffma2(acc[ 5], xa.y, w1);
                ffma2(acc[ 6], xa.y, w2); ffma2(acc[ 7], xa.y, w3);
                ffma2(acc[ 8], xb.x, w0); ffma2(acc[ 9], xb.x, w1);
                ffma2(acc[10], xb.x, w2); ffma2(acc[11], xb.x, w3);
                ffma2(acc[12], xb.y, w0); ffma2(acc[13], xb.y, w1);
                ffma2(acc[14], xb.y, w2); ffma2(acc[15], xb.y, w3);
                xa = nxa; xb = nxb; wv = nwv;
            }

            // epilogue: per rowpair rp, rows r0 (acc .x) and r0+1 (.y), 4 cols
            float4 bb = make_float4(0.f,0.f,0.f,0.f);
            if (is_self) bb = __ldg((const float4*)bias + tc);
            #pragma unroll
            for (int rp = 0; rp < 4; rp++) {
                const int r0 = 8*tr + 2*rp;
                const float2 c0 = unpack2(acc[4*rp + 0]);
                const float2 c1 = unpack2(acc[4*rp + 1]);
                const float2 c2 = unpack2(acc[4*rp + 2]);
                const float2 c3 = unpack2(acc[4*rp + 3]);
                red4(out + (size_t)s_tgt[r0]*DD + 4*tc,
                     c0.x + bb.x, c1.x + bb.y, c2.x + bb.z, c3.x + bb.w);
                red4(out + (size_t)s_tgt[r0 + 1]*DD + 4*tc,
                     c0.y + bb.x, c1.y + bb.y, c2.y + bb.z, c3.y + bb.w);
            }
        }
    }

    // ---- epilogue: last block resets barrier slots for graph replay ----
    __threadfence();
    __syncthreads();
    if (tid == 0) {
        const int done = atomicAdd(&g_bar[7], 1);
        if (done == GRID - 1) {
            #pragma unroll
            for (int p = 0; p < 8; p++) g_bar[p] = 0;
            __threadfence();
        }
    }
}

// ---------------- launch ----------------
extern "C" void kernel_launch(void* const* d_in, const int* in_sizes, int n_in,
                              void* d_out, int out_size) {
    const float* inp    = (const float*)d_in[0];
    const void*  dep    = d_in[1];
    const void*  ei     = d_in[2];
    const float* weight = (const float*)d_in[3];
    const float* wcomp  = (const float*)d_in[4];
    const float* sw     = (const float*)d_in[5];
    const float* bias   = (const float*)d_in[6];
    float* out = (float*)d_out;

    const int SMEM = (16512 + 8256 + TROWS + 8) * 4;   // ~97 KB -> 2 blocks/SM
    cudaFuncSetAttribute(k_fused, cudaFuncAttributeMaxDynamicSharedMemorySize, SMEM);

    k_fused<<<GRID, NTHR, SMEM>>>(inp, dep, ei, weight, wcomp, sw, bias, out);
}